// round 9
// baseline (speedup 1.0000x reference)
#include <cuda_runtime.h>

// Problem constants
#define BB     256      // batch
#define SEQ    196
#define DD     768
#define D4     192      // DD/4 float4 per row
#define NPOOL  20       // per pool
#define NKEYS  40       // 20 s-keys + 20 m-keys
#define KK     4        // top-k
#define BLK    3840     // LEN*H*DH = 5*12*64 floats per selected pool entry
#define BLK4   960      // BLK/4 float4 per chunk
#define PER_LB 15360    // KK * BLK floats per (layer, batch)
#define L2N    24       // num_layers * 2
#define SLICES 8        // list slices per (which,id,l)
#define GTHREADS 192    // gather threads (960 float4 = 192 x 5)

// Device-global scratch (no allocations allowed)
__device__ float g_keys[NKEYS * DD];        // normalized keys (s then m)
__device__ float g_bsum_s[BB];              // per-batch sum of top-4 s sims
__device__ float g_bsum_m[BB];              // per-batch sum of top-4 m sims
__device__ int   g_cnt[NKEYS];              // entries per (which,id)
__device__ int   g_list[NKEYS * BB * KK];   // packed (b<<2)|k entries

// ---------------------------------------------------------------------------
// Kernel 1: L2-normalize the 40 prompt keys. 40 blocks x 256 threads.
// Also zeroes the per-id list counters (graph-replay safe reset).
// ---------------------------------------------------------------------------
__global__ void normalize_keys_kernel(const float* __restrict__ skey,
                                      const float* __restrict__ mkey) {
    int p = blockIdx.x;  // 0..39
    if (threadIdx.x == 0) g_cnt[p] = 0;
    const float* src = (p < NPOOL) ? (skey + (size_t)p * DD)
                                   : (mkey + (size_t)(p - NPOOL) * DD);
    int t = threadIdx.x;  // 256 threads, 3 columns each
    float v0 = src[t], v1 = src[t + 256], v2 = src[t + 512];
    float sq = v0 * v0 + v1 * v1 + v2 * v2;

    __shared__ float sh[8];
    #pragma unroll
    for (int o = 16; o > 0; o >>= 1) sq += __shfl_down_sync(0xffffffffu, sq, o);
    if ((t & 31) == 0) sh[t >> 5] = sq;
    __syncthreads();
    if (t < 8) {
        float s = sh[t];
        #pragma unroll
        for (int o = 4; o > 0; o >>= 1) s += __shfl_down_sync(0xffu, s, o);
        if (t == 0) sh[0] = s;
    }
    __syncthreads();
    float inv = rsqrtf(fmaxf(sh[0], 1e-12f));
    float* dst = g_keys + (size_t)p * DD;
    dst[t] = v0 * inv;
    dst[t + 256] = v1 * inv;
    dst[t + 512] = v2 * inv;
}

// ---------------------------------------------------------------------------
// Kernel 2: fused per-batch mean (float4) + L2-normalize + 40 dots +
// top-4 selection; appends (b,k) entries to the inverted per-id lists.
// 256 blocks x 768 threads — all co-resident.
// ---------------------------------------------------------------------------
__global__ void batch_sim_topk_kernel(const float4* __restrict__ x) {
    int b = blockIdx.x;
    int t = threadIdx.x;   // 0..767
    int q = t / D4;        // row quarter 0..3 (49 rows each)
    int c4 = t % D4;       // float4 column 0..191

    __shared__ float4 sh4[768];     // partial sums (12 KB)
    __shared__ float4 sh_x4[D4];    // normalized mean (3 KB)
    __shared__ float  shw[8];
    __shared__ float  sh_sim[NKEYS];

    const float4* src = x + (size_t)b * (SEQ * D4) + (size_t)(q * 49) * D4 + c4;
    float4 acc = make_float4(0.f, 0.f, 0.f, 0.f);
    #pragma unroll 7
    for (int r = 0; r < 49; ++r) {
        float4 v = src[(size_t)r * D4];
        acc.x += v.x; acc.y += v.y; acc.z += v.z; acc.w += v.w;
    }
    sh4[t] = acc;
    __syncthreads();

    float sq = 0.f;
    if (t < D4) {
        float4 a = sh4[t], b1 = sh4[t + D4], c = sh4[t + 2 * D4], d = sh4[t + 3 * D4];
        float4 m;
        m.x = (a.x + b1.x + c.x + d.x) * (1.0f / SEQ);
        m.y = (a.y + b1.y + c.y + d.y) * (1.0f / SEQ);
        m.z = (a.z + b1.z + c.z + d.z) * (1.0f / SEQ);
        m.w = (a.w + b1.w + c.w + d.w) * (1.0f / SEQ);
        sh_x4[t] = m;
        sq = m.x * m.x + m.y * m.y + m.z * m.z + m.w * m.w;
    }
    #pragma unroll
    for (int o = 16; o > 0; o >>= 1) sq += __shfl_down_sync(0xffffffffu, sq, o);
    if (t < D4 && (t & 31) == 0) shw[t >> 5] = sq;
    __syncthreads();
    if (t < 32) {
        float v = (t < 6) ? shw[t] : 0.f;
        #pragma unroll
        for (int o = 4; o > 0; o >>= 1) v += __shfl_down_sync(0xffffffffu, v, o);
        if (t == 0) shw[0] = v;
    }
    __syncthreads();
    float inv = rsqrtf(fmaxf(shw[0], 1e-12f));
    if (t < D4) {
        float4 m = sh_x4[t];
        m.x *= inv; m.y *= inv; m.z *= inv; m.w *= inv;
        sh_x4[t] = m;
    }
    __syncthreads();

    int warp = t >> 5, lane = t & 31;
    for (int p = warp; p < NKEYS; p += 24) {
        const float4* kp = (const float4*)(g_keys + (size_t)p * DD);
        float dot = 0.f;
        #pragma unroll
        for (int i = lane; i < D4; i += 32) {
            float4 xv = sh_x4[i], kv = kp[i];
            dot += xv.x * kv.x + xv.y * kv.y + xv.z * kv.z + xv.w * kv.w;
        }
        #pragma unroll
        for (int o = 16; o > 0; o >>= 1) dot += __shfl_down_sync(0xffffffffu, dot, o);
        if (lane == 0) sh_sim[p] = dot;
    }
    __syncthreads();

    // Top-4 (descending, first-index ties). t=0: s-pool, t=1: m-pool.
    // Append (b,k) to the inverted list of each selected id. List order is
    // atomic-nondeterministic but every entry writes a disjoint output
    // region, so the final output is deterministic.
    if (t < 2) {
        const float* sims = sh_sim + t * NPOOL;
        float v[NPOOL];
        #pragma unroll
        for (int j = 0; j < NPOOL; ++j) v[j] = sims[j];
        float sum = 0.f;
        #pragma unroll
        for (int k = 0; k < KK; ++k) {
            float best = -1e30f; int bi = 0;
            #pragma unroll
            for (int j = 0; j < NPOOL; ++j) if (v[j] > best) { best = v[j]; bi = j; }
            sum += best;
            v[bi] = -1e30f;
            int key = t * NPOOL + bi;              // 0..39
            int slot = atomicAdd(&g_cnt[key], 1);
            g_list[key * (BB * KK) + slot] = (b << 2) | k;
        }
        if (t) g_bsum_m[b] = sum; else g_bsum_s[b] = sum;
    }
}

// ---------------------------------------------------------------------------
// Kernel 3: inverted gather. bid -> (which,id,l,slice). Block caches its
// 15 KB source chunk in registers (5 float4/thread x 192 threads), then
// streams it to every (b,k) in its list slice. Chunk reads: ~115 MB of L2
// hits total (vs 377 MB before) -> LTS stops binding, writes can approach
// the DRAM ceiling. Block 0 folds in the scalar reduction.
// Grid: 2*NPOOL*L2N*SLICES = 7680 blocks x 192 threads.
// ---------------------------------------------------------------------------
__global__ void gather_inv_kernel(const float4* __restrict__ s_prompt,
                                  const float4* __restrict__ m_prompt,
                                  float4* __restrict__ out,
                                  float* __restrict__ out_scalars) {
    int bid = blockIdx.x;
    int s   = bid % SLICES;
    int l   = (bid / SLICES) % L2N;
    int key = bid / (SLICES * L2N);     // 0..39 : which*NPOOL + id
    int which = key >= NPOOL;
    int id  = which ? key - NPOOL : key;
    int t   = threadIdx.x;              // 0..191

    if (bid == 0) {
        // Scalar reduction: 192 threads cover 256 values (t<64 take two).
        float ssum = g_bsum_s[t] + ((t < 64) ? g_bsum_s[t + GTHREADS] : 0.f);
        float msum = g_bsum_m[t] + ((t < 64) ? g_bsum_m[t + GTHREADS] : 0.f);
        __shared__ float shs[6], shm[6];
        #pragma unroll
        for (int o = 16; o > 0; o >>= 1) {
            ssum += __shfl_down_sync(0xffffffffu, ssum, o);
            msum += __shfl_down_sync(0xffffffffu, msum, o);
        }
        if ((t & 31) == 0) { shs[t >> 5] = ssum; shm[t >> 5] = msum; }
        __syncthreads();
        if (t == 0) {
            float sv = 0.f, mv = 0.f;
            #pragma unroll
            for (int w = 0; w < 6; ++w) { sv += shs[w]; mv += shm[w]; }
            out_scalars[0] = sv * (1.0f / BB);
            out_scalars[1] = mv * (1.0f / BB);
        }
    }

    int n = g_cnt[key];
    if (s >= n) return;   // empty slice

    // Cache the source chunk (l, id) in registers: 5 float4 per thread.
    const float4* prompt = which ? m_prompt : s_prompt;
    const float4* src = prompt + ((size_t)l * NPOOL + id) * BLK4;
    float4 v0 = __ldg(&src[t]);
    float4 v1 = __ldg(&src[t + GTHREADS]);
    float4 v2 = __ldg(&src[t + 2 * GTHREADS]);
    float4 v3 = __ldg(&src[t + 3 * GTHREADS]);
    float4 v4 = __ldg(&src[t + 4 * GTHREADS]);

    const size_t which_off = (size_t)which * ((size_t)L2N * BB * (PER_LB));
    const int* list = g_list + key * (BB * KK);

    for (int e = s; e < n; e += SLICES) {
        int ent = list[e];
        int b = ent >> 2;
        int k = ent & 3;
        float4* dst = out + (which_off + ((size_t)l * BB + b) * PER_LB
                             + (size_t)k * BLK) / 4;
        __stcs(&dst[t],                v0);
        __stcs(&dst[t + GTHREADS],     v1);
        __stcs(&dst[t + 2 * GTHREADS], v2);
        __stcs(&dst[t + 3 * GTHREADS], v3);
        __stcs(&dst[t + 4 * GTHREADS], v4);
    }
}

// ---------------------------------------------------------------------------
extern "C" void kernel_launch(void* const* d_in, const int* in_sizes, int n_in,
                              void* d_out, int out_size) {
    const float* x_embed = (const float*)d_in[0];  // [256,196,768]
    const float* s_prompt = (const float*)d_in[1]; // [24,20,5,12,64]
    const float* m_prompt = (const float*)d_in[2]; // [24,20,5,12,64]
    const float* s_key = (const float*)d_in[3];    // [20,768]
    const float* m_key = (const float*)d_in[4];    // [20,768]
    float* out = (float*)d_out;

    const size_t S_ELEMS = (size_t)L2N * BB * PER_LB;  // 94,371,840
    float* out_scalars = out + 2 * S_ELEMS;

    normalize_keys_kernel<<<NKEYS, 256>>>(s_key, m_key);
    batch_sim_topk_kernel<<<BB, 768>>>((const float4*)x_embed);
    gather_inv_kernel<<<2 * NPOOL * L2N * SLICES, GTHREADS>>>(
        (const float4*)s_prompt, (const float4*)m_prompt,
        (float4*)out, out_scalars);
}

// round 10
// speedup vs baseline: 1.0435x; 1.0435x over previous
#include <cuda_runtime.h>

// Problem constants
#define BB     256      // batch
#define SEQ    196
#define DD     768
#define D4     192      // DD/4 float4 per row
#define NPOOL  20       // per pool
#define NKEYS  40       // 20 s-keys + 20 m-keys
#define KK     4        // top-k
#define BLK    3840     // LEN*H*DH = 5*12*64 floats per selected pool entry
#define PER_LB 15360    // KK * BLK floats per (layer, batch)
#define L2N    24       // num_layers * 2

// Device-global scratch (no allocations allowed)
__device__ int   g_sidx[BB * KK];
__device__ int   g_midx[BB * KK];
__device__ float g_bsum_s[BB];         // per-batch sum of top-4 s sims
__device__ float g_bsum_m[BB];         // per-batch sum of top-4 m sims

// ---------------------------------------------------------------------------
// Kernel 1: fused per-batch mean (float4, 4 row-groups of 49) + L2-normalize
// + 40 similarity dots with ON-THE-FLY key normalization (accumulate k.x and
// k.k together; sim = dot * rsqrt(max(k.k, eps))) + in-block top-4 selection.
// 256 blocks x 768 threads — all co-resident (2/SM). No separate key kernel.
// ---------------------------------------------------------------------------
__global__ void batch_sim_topk_kernel(const float4* __restrict__ x,
                                      const float4* __restrict__ skey,
                                      const float4* __restrict__ mkey) {
    int b = blockIdx.x;
    int t = threadIdx.x;   // 0..767
    int q = t / D4;        // row quarter 0..3 (49 rows each)
    int c4 = t % D4;       // float4 column 0..191

    __shared__ float4 sh4[768];     // partial sums (12 KB)
    __shared__ float4 sh_x4[D4];    // normalized mean (3 KB)
    __shared__ float  shw[8];
    __shared__ float  sh_sim[NKEYS];

    const float4* src = x + (size_t)b * (SEQ * D4) + (size_t)(q * 49) * D4 + c4;
    float4 acc = make_float4(0.f, 0.f, 0.f, 0.f);
    #pragma unroll 7
    for (int r = 0; r < 49; ++r) {
        float4 v = src[(size_t)r * D4];
        acc.x += v.x; acc.y += v.y; acc.z += v.z; acc.w += v.w;
    }
    sh4[t] = acc;
    __syncthreads();

    // Combine 4 partials -> mean; squared-norm partial per thread (t < 192)
    float sq = 0.f;
    if (t < D4) {
        float4 a = sh4[t], b1 = sh4[t + D4], c = sh4[t + 2 * D4], d = sh4[t + 3 * D4];
        float4 m;
        m.x = (a.x + b1.x + c.x + d.x) * (1.0f / SEQ);
        m.y = (a.y + b1.y + c.y + d.y) * (1.0f / SEQ);
        m.z = (a.z + b1.z + c.z + d.z) * (1.0f / SEQ);
        m.w = (a.w + b1.w + c.w + d.w) * (1.0f / SEQ);
        sh_x4[t] = m;
        sq = m.x * m.x + m.y * m.y + m.z * m.z + m.w * m.w;
    }
    #pragma unroll
    for (int o = 16; o > 0; o >>= 1) sq += __shfl_down_sync(0xffffffffu, sq, o);
    if (t < D4 && (t & 31) == 0) shw[t >> 5] = sq;
    __syncthreads();
    if (t < 32) {
        float v = (t < 6) ? shw[t] : 0.f;
        #pragma unroll
        for (int o = 4; o > 0; o >>= 1) v += __shfl_down_sync(0xffffffffu, v, o);
        if (t == 0) shw[0] = v;
    }
    __syncthreads();
    float inv = rsqrtf(fmaxf(shw[0], 1e-12f));
    if (t < D4) {
        float4 m = sh_x4[t];
        m.x *= inv; m.y *= inv; m.z *= inv; m.w *= inv;
        sh_x4[t] = m;
    }
    __syncthreads();

    // 24 warps handle 40 pools: raw-key dot + key squared-norm in one pass.
    int warp = t >> 5, lane = t & 31;
    for (int p = warp; p < NKEYS; p += 24) {
        const float4* kp = (p < NPOOL) ? (skey + (size_t)p * D4)
                                       : (mkey + (size_t)(p - NPOOL) * D4);
        float dot = 0.f, kk = 0.f;
        #pragma unroll
        for (int i = lane; i < D4; i += 32) {
            float4 xv = sh_x4[i], kv = __ldg(&kp[i]);
            dot += xv.x * kv.x + xv.y * kv.y + xv.z * kv.z + xv.w * kv.w;
            kk  += kv.x * kv.x + kv.y * kv.y + kv.z * kv.z + kv.w * kv.w;
        }
        #pragma unroll
        for (int o = 16; o > 0; o >>= 1) {
            dot += __shfl_down_sync(0xffffffffu, dot, o);
            kk  += __shfl_down_sync(0xffffffffu, kk, o);
        }
        if (lane == 0) sh_sim[p] = dot * rsqrtf(fmaxf(kk, 1e-12f));
    }
    __syncthreads();

    // Top-4 (descending, first-index ties — strict > scan from j=0).
    // Thread 0 handles s-pool, thread 1 handles m-pool.
    if (t < 2) {
        const float* sims = sh_sim + t * NPOOL;
        int* idx = t ? g_midx : g_sidx;
        float v[NPOOL];
        #pragma unroll
        for (int j = 0; j < NPOOL; ++j) v[j] = sims[j];
        float sum = 0.f;
        #pragma unroll
        for (int k = 0; k < KK; ++k) {
            float best = -1e30f; int bi = 0;
            #pragma unroll
            for (int j = 0; j < NPOOL; ++j) if (v[j] > best) { best = v[j]; bi = j; }
            idx[b * KK + k] = bi;
            sum += best;
            v[bi] = -1e30f;
        }
        if (t) g_bsum_m[b] = sum; else g_bsum_s[b] = sum;
    }
}

// ---------------------------------------------------------------------------
// Kernel 2: the gather — exact R8 configuration (measured 58.98us/launch at
// the DRAM write ceiling). Streaming stores (__stcs), __ldg prompt reads.
// Block 0 of the s-launch folds in the scalar reduction.
// Grid: 6144 blocks x 256 threads, two launches.
// ---------------------------------------------------------------------------
__global__ void gather_kernel(const float4* __restrict__ prompt,
                              float4* __restrict__ out, int which,
                              float* __restrict__ out_scalars) {
    int lb = blockIdx.x;
    int l = lb >> 8;          // / 256
    int b = lb & 255;
    int t = threadIdx.x;

    if (which == 0 && lb == 0) {
        float ssum = g_bsum_s[t];
        float msum = g_bsum_m[t];
        __shared__ float shs[8], shm[8];
        #pragma unroll
        for (int o = 16; o > 0; o >>= 1) {
            ssum += __shfl_down_sync(0xffffffffu, ssum, o);
            msum += __shfl_down_sync(0xffffffffu, msum, o);
        }
        if ((t & 31) == 0) { shs[t >> 5] = ssum; shm[t >> 5] = msum; }
        __syncthreads();
        if (t < 8) {
            float s = shs[t], m = shm[t];
            #pragma unroll
            for (int o = 4; o > 0; o >>= 1) {
                s += __shfl_down_sync(0xffu, s, o);
                m += __shfl_down_sync(0xffu, m, o);
            }
            if (t == 0) {
                out_scalars[0] = s * (1.0f / BB);
                out_scalars[1] = m * (1.0f / BB);
            }
        }
    }

    const int* idx = which ? g_midx : g_sidx;
    int i0 = idx[b * KK + 0], i1 = idx[b * KK + 1],
        i2 = idx[b * KK + 2], i3 = idx[b * KK + 3];
    int ids[4] = {i0, i1, i2, i3};

    float4* dst = out + (size_t)lb * (PER_LB / 4);
    #pragma unroll
    for (int k = 0; k < 4; ++k) {
        const float4* src = prompt + ((size_t)l * NPOOL + ids[k]) * (BLK / 4);
        float4* dk = dst + k * (BLK / 4);
        for (int j = t; j < BLK / 4; j += 256) {  // 960 float4 per chunk
            float4 v = __ldg(&src[j]);
            __stcs(&dk[j], v);                    // streaming store (st.global.cs)
        }
    }
}

// ---------------------------------------------------------------------------
extern "C" void kernel_launch(void* const* d_in, const int* in_sizes, int n_in,
                              void* d_out, int out_size) {
    const float* x_embed = (const float*)d_in[0];  // [256,196,768]
    const float* s_prompt = (const float*)d_in[1]; // [24,20,5,12,64]
    const float* m_prompt = (const float*)d_in[2]; // [24,20,5,12,64]
    const float* s_key = (const float*)d_in[3];    // [20,768]
    const float* m_key = (const float*)d_in[4];    // [20,768]
    float* out = (float*)d_out;

    const size_t S_ELEMS = (size_t)L2N * BB * PER_LB;  // 94,371,840
    float* out_scalars = out + 2 * S_ELEMS;

    batch_sim_topk_kernel<<<BB, 768>>>((const float4*)x_embed,
                                       (const float4*)s_key,
                                       (const float4*)m_key);
    gather_kernel<<<L2N * BB, 256>>>((const float4*)s_prompt,
                                     (float4*)out, 0, out_scalars);
    gather_kernel<<<L2N * BB, 256>>>((const float4*)m_prompt,
                                     (float4*)(out + S_ELEMS), 1, out_scalars);
}